// round 16
// baseline (speedup 1.0000x reference)
#include <cuda_runtime.h>
#include <cuda_fp16.h>
#include <cstdint>

// ---------------------------------------------------------------------------
// Problem constants
// ---------------------------------------------------------------------------
#define N_ROWS 100000
#define HID    512
#define D_IN   64
#define PH     16
#define NOBS   50000
#define K1     1024      // PH*D
#define K2     512       // HID
#define H3     1536      // 3*HID
#define MTILES ((NOBS + 127) / 128)   // 391
#define SCAN_BLK 512
#define NSB ((NOBS + SCAN_BLK - 1) / SCAN_BLK)   // 98

// ---------------------------------------------------------------------------
// Scratch (__device__ globals — sanctioned scratch path, no runtime allocs)
// ---------------------------------------------------------------------------
__device__ __half g_Wih_h[(size_t)H3 * K1];     //  3 MB
__device__ __half g_Whh_h[(size_t)H3 * K2];     //  1.5 MB
__device__ __half g_gruin[(size_t)NOBS * K1];   // 100 MB (compacted rows)
__device__ __half g_hgat [(size_t)NOBS * K2];   //  50 MB (compacted rows)
__device__ __half g_gi   [(size_t)NOBS * H3];   // r,z: ir+hr sums; n: in
__device__ __half g_gh   [(size_t)NOBS * H3];   // only cols [1024,1536) used: hn
__device__ float  g_loss;
__device__ int    g_blkcnt[NSB];
__device__ int    g_blkoff[NSB];
__device__ int    g_Mc;                 // number of last-occurrence rows
__device__ int    g_slot[NOBS];         // obs row -> compact slot
__device__ int    g_cidx[NOBS];         // compact slot -> h index
__device__ int    g_rowslot[N_ROWS];    // h row -> compact slot (or -1)

// ---------------------------------------------------------------------------
// Helpers
// ---------------------------------------------------------------------------
__device__ __forceinline__ uint32_t smem_to_u32(const void* smem_ptr) {
    uint32_t addr;
    asm("{ .reg .u64 tmp; cvta.to.shared.u64 tmp, %1; cvt.u32.u64 %0, tmp; }"
        : "=r"(addr) : "l"(smem_ptr));
    return addr;
}

__device__ __forceinline__ void cp_async16(uint32_t dst, const void* src, int src_bytes) {
    asm volatile("cp.async.cg.shared.global [%0], [%1], 16, %2;"
                 :: "r"(dst), "l"(src), "r"(src_bytes));
}
#define CP_ASYNC_COMMIT() asm volatile("cp.async.commit_group;" ::: "memory")
#define CP_ASYNC_WAIT_2() asm volatile("cp.async.wait_group 2;" ::: "memory")

#define LDMATRIX_X4(r0, r1, r2, r3, addr) \
    asm volatile("ldmatrix.sync.aligned.m8n8.x4.shared.b16 {%0,%1,%2,%3}, [%4];" \
                 : "=r"(r0), "=r"(r1), "=r"(r2), "=r"(r3) : "r"(addr))

#define MMA_16816(d, a0, a1, a2, a3, b0, b1) \
    asm volatile("mma.sync.aligned.m16n8k16.row.col.f32.f16.f16.f32 " \
                 "{%0,%1,%2,%3}, {%4,%5,%6,%7}, {%8,%9}, {%0,%1,%2,%3};" \
                 : "+f"((d)[0]), "+f"((d)[1]), "+f"((d)[2]), "+f"((d)[3]) \
                 : "r"(a0), "r"(a1), "r"(a2), "r"(a3), "r"(b0), "r"(b1))

__device__ __forceinline__ int is_last(const int* iobs, int r) {
    return (r == NOBS - 1) || (iobs[r + 1] != iobs[r]);
}

// ---------------------------------------------------------------------------
// 1. initA: scanA (blocks < NSB) + loss/rowslot init + weight convert
// ---------------------------------------------------------------------------
__global__ void __launch_bounds__(512) initA_kernel(
    const int* __restrict__ iobs,
    const float* __restrict__ wih, const float* __restrict__ whh) {
    __shared__ int sh[SCAN_BLK];

    if (blockIdx.x < NSB) {
        const int r = blockIdx.x * SCAN_BLK + threadIdx.x;
        sh[threadIdx.x] = (r < NOBS) ? is_last(iobs, r) : 0;
        __syncthreads();
        for (int s = SCAN_BLK / 2; s > 0; s >>= 1) {
            if (threadIdx.x < s) sh[threadIdx.x] += sh[threadIdx.x + s];
            __syncthreads();
        }
        if (threadIdx.x == 0) g_blkcnt[blockIdx.x] = sh[0];
        return;
    }

    const int b = blockIdx.x - NSB;
    const int tid = b * 512 + threadIdx.x;
    const int nthr = 256 * 512;
    if (tid == 0) g_loss = 0.0f;
    for (int i = tid; i < N_ROWS; i += nthr) g_rowslot[i] = -1;

    const int q1 = H3 * K1 / 4;
    const int q2 = H3 * K2 / 4;
    for (int i = tid; i < q1 + q2; i += nthr) {
        float4 v;
        __half2* dst;
        if (i < q1) {
            v = reinterpret_cast<const float4*>(wih)[i];
            dst = reinterpret_cast<__half2*>(&g_Wih_h[(size_t)i * 4]);
        } else {
            v = reinterpret_cast<const float4*>(whh)[i - q1];
            dst = reinterpret_cast<__half2*>(&g_Whh_h[(size_t)(i - q1) * 4]);
        }
        dst[0] = __floats2half2_rn(v.x, v.y);
        dst[1] = __floats2half2_rn(v.z, v.w);
    }
}

// ---------------------------------------------------------------------------
// 2-3. Scan finish
// ---------------------------------------------------------------------------
__global__ void scanB_kernel() {
    if (threadIdx.x == 0) {
        int acc = 0;
        for (int b = 0; b < NSB; b++) { g_blkoff[b] = acc; acc += g_blkcnt[b]; }
        g_Mc = acc;
    }
}

__global__ void __launch_bounds__(SCAN_BLK) scanC_kernel(const int* __restrict__ iobs) {
    __shared__ int sh[SCAN_BLK];
    const int r = blockIdx.x * SCAN_BLK + threadIdx.x;
    const int last = (r < NOBS) ? is_last(iobs, r) : 0;
    sh[threadIdx.x] = last;
    __syncthreads();
    for (int off = 1; off < SCAN_BLK; off <<= 1) {
        int v = (threadIdx.x >= off) ? sh[threadIdx.x - off] : 0;
        __syncthreads();
        sh[threadIdx.x] += v;
        __syncthreads();
    }
    if (r < NOBS) {
        const int slot = g_blkoff[blockIdx.x] + sh[threadIdx.x] - last;  // exclusive
        g_slot[r] = slot;
        if (last) {
            const int i = iobs[r];
            g_cidx[slot] = i;
            g_rowslot[i] = slot;
        }
    }
}

// ---------------------------------------------------------------------------
// 4. Prep: loss (all rows) + feats einsum (last rows, compacted) -> g_gruin
//    Transposed, conflict-free smem staging.
// ---------------------------------------------------------------------------
__global__ void __launch_bounds__(256) prep_kernel(
    const float* __restrict__ p, const float* __restrict__ X,
    const float* __restrict__ M, const int* __restrict__ iobs,
    const float* __restrict__ wprep, const float* __restrict__ bprep) {
    __shared__ float swt[64 * D_IN];   // [k = f*16+j][d]
    __shared__ float sbt[PH * D_IN];   // [j][d]
    __shared__ float sred[256];

    for (int i = threadIdx.x; i < D_IN * 64; i += 256) {
        const int d = i >> 6, k = i & 63;
        swt[k * 64 + d] = wprep[i];
    }
    for (int i = threadIdx.x; i < D_IN * PH; i += 256) {
        const int d = i >> 4, j = i & 15;
        sbt[j * 64 + d] = bprep[i];
    }
    __syncthreads();

    const int d   = threadIdx.x & 63;
    const int sub = threadIdx.x >> 6;   // 0..3
    const int base = blockIdx.x * 32;
    float lacc = 0.0f;

    for (int rr = sub; rr < 32; rr += 4) {
        const int r = base + rr;
        if (r >= NOBS) continue;
        const int i = iobs[r];
        const float mean = p[(size_t)i * 128 + d];
        const float var  = fabsf(p[(size_t)i * 128 + 64 + d]) + 1e-6f;
        const float x    = X[(size_t)r * 64 + d];
        const float m    = M[(size_t)r * 64 + d];
        const float rsv  = rsqrtf(var);
        const float err  = (x - mean) * rsv;
        lacc += 0.5f * (err * err + logf(var)) * m;

        if (!is_last(iobs, r)) continue;

        __half2 hv[8];
        #pragma unroll
        for (int j = 0; j < 16; j += 2) {
            float v0 = sbt[j * 64 + d];
            v0 = fmaf(x,    swt[(j)      * 64 + d], v0);
            v0 = fmaf(mean, swt[(16 + j) * 64 + d], v0);
            v0 = fmaf(var,  swt[(32 + j) * 64 + d], v0);
            v0 = fmaf(err,  swt[(48 + j) * 64 + d], v0);
            float v1 = sbt[(j + 1) * 64 + d];
            v1 = fmaf(x,    swt[(j + 1)      * 64 + d], v1);
            v1 = fmaf(mean, swt[(16 + j + 1) * 64 + d], v1);
            v1 = fmaf(var,  swt[(32 + j + 1) * 64 + d], v1);
            v1 = fmaf(err,  swt[(48 + j + 1) * 64 + d], v1);
            v0 = fmaxf(v0, 0.0f) * m;
            v1 = fmaxf(v1, 0.0f) * m;
            hv[j >> 1] = __floats2half2_rn(v0, v1);
        }
        const int slot = g_slot[r];
        uint4* dst = reinterpret_cast<uint4*>(&g_gruin[(size_t)slot * K1 + d * 16]);
        dst[0] = *reinterpret_cast<uint4*>(&hv[0]);
        dst[1] = *reinterpret_cast<uint4*>(&hv[4]);
    }

    sred[threadIdx.x] = lacc;
    __syncthreads();
    for (int s = 128; s > 0; s >>= 1) {
        if (threadIdx.x < s) sred[threadIdx.x] += sred[threadIdx.x + s];
        __syncthreads();
    }
    if (threadIdx.x == 0) atomicAdd(&g_loss, sred[0]);
}

// ---------------------------------------------------------------------------
// 5. Gather h[cidx[s]] -> fp16 (lean, no smem, MLP=2: 64 thr/row, 2 float4 ea)
// ---------------------------------------------------------------------------
__global__ void __launch_bounds__(256) gather_h_kernel(const float* __restrict__ h) {
    const int idx = blockIdx.x * 256 + threadIdx.x;
    const int s = idx >> 6;              // 64 threads per slot
    if (s >= g_Mc) return;
    const int t = idx & 63;
    const int i = g_cidx[s];
    const float4* src = reinterpret_cast<const float4*>(&h[(size_t)i * HID]);
    const float4 v0 = src[t * 2];
    const float4 v1 = src[t * 2 + 1];
    __half2 hv[4];
    hv[0] = __floats2half2_rn(v0.x, v0.y);
    hv[1] = __floats2half2_rn(v0.z, v0.w);
    hv[2] = __floats2half2_rn(v1.x, v1.y);
    hv[3] = __floats2half2_rn(v1.z, v1.w);
    *reinterpret_cast<uint4*>(&g_hgat[(size_t)s * K2 + t * 8]) =
        *reinterpret_cast<uint4*>(hv);
}

// ---------------------------------------------------------------------------
// 6. HMMA GEMM (roofline mainloop, dynamic M = g_Mc)
//    fuse=0 (GEMM1): C[row,col] = acc                   (C = gi)
//    fuse=1 (GEMM2): n0 < 1024 -> C[row,col] += acc     (gi accumulates ir+hr)
//                    n0 >= 1024 -> Cn[row,col] = acc    (gh holds hn)
// ---------------------------------------------------------------------------
#define STAGES       4
#define STAGE_BYTES  20480          // A 10240 + B 10240
#define SM_B_OFF     10240

__device__ __forceinline__ void load_stage(uint32_t sm, int stage,
                                           const __half* __restrict__ A,
                                           const __half* __restrict__ B,
                                           int m0, int n0, int K, int kc,
                                           int tid, int Mrows) {
    const uint32_t base = sm + stage * STAGE_BYTES;
    #pragma unroll
    for (int it = 0; it < 4; it++) {
        const int c = tid + it * 256;           // 0..1023
        const int cc = c & 511;
        const int row = cc >> 2, ch = cc & 3;   // 128 rows x 4 x 16B
        if (c < 512) {  // A
            const int rg = m0 + row;
            const int rc = rg < Mrows ? rg : (Mrows - 1);
            const void* src = A + (size_t)rc * K + kc * 32 + ch * 8;
            cp_async16(base + row * 80 + ch * 16, src, rg < Mrows ? 16 : 0);
        } else {        // B (always in range)
            const void* src = B + (size_t)(n0 + row) * K + kc * 32 + ch * 8;
            cp_async16(base + SM_B_OFF + row * 80 + ch * 16, src, 16);
        }
    }
}

__global__ void __launch_bounds__(256, 2) gemm_hmma_kernel(
    const __half* __restrict__ A, const __half* __restrict__ B,
    __half* __restrict__ C, __half* __restrict__ Cn, int K, int fuse) {
    const int Mrows = g_Mc;
    const int m0 = blockIdx.y * 128;
    if (m0 >= Mrows) return;                      // surplus m-tiles exit

    extern __shared__ __align__(128) char smem[];   // STAGES * STAGE_BYTES
    const uint32_t sm = smem_to_u32(smem);

    const int tid  = threadIdx.x;
    const int lane = tid & 31;
    const int wid  = tid >> 5;
    const int warp_m = wid & 3;
    const int warp_n = wid >> 2;

    const int n0 = blockIdx.x * 128;
    const int nk = K >> 5;

    const uint32_t lrow = lane & 15;
    const uint32_t lcol = (lane >> 4) << 4;
    const uint32_t a_off = (warp_m * 32 + lrow) * 80 + lcol;
    const uint32_t b_off = SM_B_OFF + (warp_n * 64 + lrow) * 80 + lcol;

    float acc[2][8][4];
    #pragma unroll
    for (int mt = 0; mt < 2; mt++)
        #pragma unroll
        for (int nt = 0; nt < 8; nt++)
            #pragma unroll
            for (int e = 0; e < 4; e++) acc[mt][nt][e] = 0.0f;

    #pragma unroll
    for (int s = 0; s < 3; s++) {
        load_stage(sm, s, A, B, m0, n0, K, s, tid, Mrows);
        CP_ASYNC_COMMIT();
    }

    for (int kc = 0; kc < nk; kc++) {
        const int buf = kc & 3;
        CP_ASYNC_WAIT_2();
        __syncthreads();

        if (kc + 3 < nk)
            load_stage(sm, (kc + 3) & 3, A, B, m0, n0, K, kc + 3, tid, Mrows);
        CP_ASYNC_COMMIT();

        const uint32_t sA = sm + buf * STAGE_BYTES;

        #pragma unroll
        for (int ks = 0; ks < 2; ks++) {
            const uint32_t k0b = ks * 32;
            uint32_t a[2][4];
            LDMATRIX_X4(a[0][0], a[0][1], a[0][2], a[0][3], sA + a_off + k0b);
            LDMATRIX_X4(a[1][0], a[1][1], a[1][2], a[1][3], sA + a_off + 1280 + k0b);
            uint32_t b[8][2];
            #pragma unroll
            for (int nb = 0; nb < 4; nb++) {
                uint32_t r0, r1, r2, r3;
                LDMATRIX_X4(r0, r1, r2, r3, sA + b_off + nb * 1280 + k0b);
                b[2 * nb][0] = r0; b[2 * nb][1] = r2;
                b[2 * nb + 1][0] = r1; b[2 * nb + 1][1] = r3;
            }
            #pragma unroll
            for (int mt = 0; mt < 2; mt++)
                #pragma unroll
                for (int nt = 0; nt < 8; nt++)
                    MMA_16816(acc[mt][nt],
                              a[mt][0], a[mt][1], a[mt][2], a[mt][3],
                              b[nt][0], b[nt][1]);
        }
    }

    // epilogue
    const bool rmw = fuse && (n0 < 1024);
    __half* Cb = (fuse && n0 >= 1024) ? Cn : C;
    #pragma unroll
    for (int mt = 0; mt < 2; mt++) {
        const int r0 = m0 + warp_m * 32 + mt * 16 + (lane >> 2);
        #pragma unroll
        for (int nt = 0; nt < 8; nt++) {
            const int col = n0 + warp_n * 64 + nt * 8 + (lane & 3) * 2;
            if (r0 < Mrows) {
                __half2* ptr = reinterpret_cast<__half2*>(&Cb[(size_t)r0 * H3 + col]);
                float a0 = acc[mt][nt][0], a1 = acc[mt][nt][1];
                if (rmw) { float2 o = __half22float2(*ptr); a0 += o.x; a1 += o.y; }
                *ptr = __floats2half2_rn(a0, a1);
            }
            if (r0 + 8 < Mrows) {
                __half2* ptr = reinterpret_cast<__half2*>(&Cb[(size_t)(r0 + 8) * H3 + col]);
                float a2 = acc[mt][nt][2], a3 = acc[mt][nt][3];
                if (rmw) { float2 o = __half22float2(*ptr); a2 += o.x; a3 += o.y; }
                *ptr = __floats2half2_rn(a2, a3);
            }
        }
    }
}

// ---------------------------------------------------------------------------
// 7. Unified output v2: 8 rows/block (256 thr), 32 thr/row, 4 float4 per
//    thread (MLP=4) — higher ILP to push the latency-bound output pass
//    toward bandwidth. gi: [0,512)=ir+hr, [512,1024)=iz+hz, [1024,1536)=in;
//    gh: [1024,1536)=hn.
// ---------------------------------------------------------------------------
__global__ void __launch_bounds__(256) out_kernel(
    const float* __restrict__ h,
    const float* __restrict__ bih, const float* __restrict__ bhh,
    float* __restrict__ out, int has_loss) {
    if (has_loss && blockIdx.x == 0 && threadIdx.x == 0)
        out[(size_t)N_ROWS * HID] = g_loss;

    const int row = blockIdx.x * 8 + (threadIdx.x >> 5);
    if (row >= N_ROWS) return;
    const int t = threadIdx.x & 31;             // 32 thr/row, 4 float4 each
    const int s = g_rowslot[row];

    const float4* hrow4 = reinterpret_cast<const float4*>(&h[(size_t)row * HID]);
    float4* orow4 = reinterpret_cast<float4*>(&out[(size_t)row * HID]);

    if (s < 0) {                                 // not updated: plain copy
        const float4 c0 = hrow4[t];
        const float4 c1 = hrow4[t + 32];
        const float4 c2 = hrow4[t + 64];
        const float4 c3 = hrow4[t + 96];
        orow4[t]      = c0;
        orow4[t + 32] = c1;
        orow4[t + 64] = c2;
        orow4[t + 96] = c3;
        return;
    }

    const __half2* gi = reinterpret_cast<const __half2*>(&g_gi[(size_t)s * H3]);
    const __half2* gh = reinterpret_cast<const __half2*>(&g_gh[(size_t)s * H3]);
    const float4* b_ih4 = reinterpret_cast<const float4*>(bih);
    const float4* b_hh4 = reinterpret_cast<const float4*>(bhh);

    #pragma unroll
    for (int k = 0; k < 4; k++) {
        const int q = t + k * 32;               // float4 index within row
        const int j0 = 2 * q, j1 = 2 * q + 1;
        const float2 sr0 = __half22float2(gi[j0]),       sr1 = __half22float2(gi[j1]);
        const float2 sz0 = __half22float2(gi[256 + j0]), sz1 = __half22float2(gi[256 + j1]);
        const float2 in0 = __half22float2(gi[512 + j0]), in1 = __half22float2(gi[512 + j1]);
        const float2 hn0 = __half22float2(gh[512 + j0]), hn1 = __half22float2(gh[512 + j1]);
        const float4 bir = b_ih4[q],       bhr = b_hh4[q];
        const float4 biz = b_ih4[128 + q], bhz = b_hh4[128 + q];
        const float4 bin = b_ih4[256 + q], bhn = b_hh4[256 + q];
        const float4 hp = hrow4[q];

        const float irs[4] = {sr0.x + bir.x + bhr.x, sr0.y + bir.y + bhr.y,
                              sr1.x + bir.z + bhr.z, sr1.y + bir.w + bhr.w};
        const float izs[4] = {sz0.x + biz.x + bhz.x, sz0.y + biz.y + bhz.y,
                              sz1.x + biz.z + bhz.z, sz1.y + biz.w + bhz.w};
        const float ins[4] = {in0.x + bin.x, in0.y + bin.y, in1.x + bin.z, in1.y + bin.w};
        const float hns[4] = {hn0.x + bhn.x, hn0.y + bhn.y, hn1.x + bhn.z, hn1.y + bhn.w};

        float rr[4], zz[4], nn[4];
        #pragma unroll
        for (int e = 0; e < 4; e++) {
            rr[e] = 1.0f / (1.0f + expf(-irs[e]));
            zz[e] = 1.0f / (1.0f + expf(-izs[e]));
            nn[e] = tanhf(ins[e] + rr[e] * hns[e]);
        }
        float4 o;
        o.x = (1.0f - zz[0]) * nn[0] + zz[0] * hp.x;
        o.y = (1.0f - zz[1]) * nn[1] + zz[1] * hp.y;
        o.z = (1.0f - zz[2]) * nn[2] + zz[2] * hp.z;
        o.w = (1.0f - zz[3]) * nn[3] + zz[3] * hp.w;
        orow4[q] = o;
    }
}

// ---------------------------------------------------------------------------
// Launch — single stream, 8 nodes
// ---------------------------------------------------------------------------
extern "C" void kernel_launch(void* const* d_in, const int* in_sizes, int n_in,
                              void* d_out, int out_size) {
    const float* h     = (const float*)d_in[0];
    const float* p     = (const float*)d_in[1];
    const float* X     = (const float*)d_in[2];
    const float* M     = (const float*)d_in[3];
    const int*   iobs  = (const int*)  d_in[4];
    const float* wprep = (const float*)d_in[5];
    const float* bprep = (const float*)d_in[6];
    const float* wih   = (const float*)d_in[7];
    const float* whh   = (const float*)d_in[8];
    const float* bih   = (const float*)d_in[9];
    const float* bhh   = (const float*)d_in[10];
    float* out = (float*)d_out;

    static bool init_done = false;
    if (!init_done) {
        cudaFuncSetAttribute(gemm_hmma_kernel,
                             cudaFuncAttributeMaxDynamicSharedMemorySize,
                             STAGES * STAGE_BYTES);
        init_done = true;
    }

    __half *d_gruin, *d_hgat, *d_gi, *d_gh, *d_wih, *d_whh;
    cudaGetSymbolAddress((void**)&d_gruin, g_gruin);
    cudaGetSymbolAddress((void**)&d_hgat,  g_hgat);
    cudaGetSymbolAddress((void**)&d_gi,    g_gi);
    cudaGetSymbolAddress((void**)&d_gh,    g_gh);
    cudaGetSymbolAddress((void**)&d_wih,   g_Wih_h);
    cudaGetSymbolAddress((void**)&d_whh,   g_Whh_h);

    // 1. scanA + init (loss, rowslot) + weight convert
    initA_kernel<<<NSB + 256, 512>>>(iobs, wih, whh);

    // 2-3. scan finish
    scanB_kernel<<<1, 32>>>();
    scanC_kernel<<<NSB, SCAN_BLK>>>(iobs);

    // 4. prep: loss + gru_in (compacted, conflict-free smem)
    prep_kernel<<<(NOBS + 31) / 32, 256>>>(p, X, M, iobs, wprep, bprep);

    // 5. gather h[cidx] -> fp16 (lean, vectorized)
    gather_h_kernel<<<(NOBS * 64 + 255) / 256, 256>>>(h);

    // 6. gi = gru_in @ Wih^T   (Mc x 1536 x 1024)
    gemm_hmma_kernel<<<dim3(12, MTILES), 256, STAGES * STAGE_BYTES>>>(
        d_gruin, d_wih, d_gi, d_gh, K1, 0);

    // 7. gh-pass: r,z tiles accumulate into gi; n tiles write hn into gh
    gemm_hmma_kernel<<<dim3(12, MTILES), 256, STAGES * STAGE_BYTES>>>(
        d_hgat, d_whh, d_gi, d_gh, K2, 1);

    // 8. unified output (+loss)
    out_kernel<<<(N_ROWS + 7) / 8, 256>>>(h, bih, bhh, out,
                                          out_size > N_ROWS * HID ? 1 : 0);
}

// round 17
// speedup vs baseline: 1.0166x; 1.0166x over previous
#include <cuda_runtime.h>
#include <cuda_fp16.h>
#include <cstdint>

// ---------------------------------------------------------------------------
// Problem constants
// ---------------------------------------------------------------------------
#define N_ROWS 100000
#define HID    512
#define D_IN   64
#define PH     16
#define NOBS   50000
#define K1     1024      // PH*D
#define K2     512       // HID
#define H3     1536      // 3*HID
#define MTILES ((NOBS + 127) / 128)   // 391
#define SCAN_BLK 512
#define NSB ((NOBS + SCAN_BLK - 1) / SCAN_BLK)   // 98
#define NK_TOT 48        // 32 chunks (K1) + 16 chunks (K2)

// ---------------------------------------------------------------------------
// Scratch (__device__ globals — sanctioned scratch path, no runtime allocs)
// ---------------------------------------------------------------------------
__device__ __half g_Wih_h[(size_t)H3 * K1];     //  3 MB
__device__ __half g_Whh_h[(size_t)H3 * K2];     //  1.5 MB
__device__ __half g_gruin[(size_t)NOBS * K1];   // 100 MB (compacted rows)
__device__ __half g_hgat [(size_t)NOBS * K2];   //  50 MB (compacted rows)
__device__ __half g_gi   [(size_t)NOBS * H3];   // r,z: ir+hr sums; n: in
__device__ __half g_gh   [(size_t)NOBS * H3];   // only cols [1024,1536) used: hn
__device__ float  g_loss;
__device__ int    g_blkcnt[NSB];
__device__ int    g_blkoff[NSB];
__device__ int    g_Mc;                 // number of last-occurrence rows
__device__ int    g_slot[NOBS];         // obs row -> compact slot
__device__ int    g_cidx[NOBS];         // compact slot -> h index
__device__ int    g_rowslot[N_ROWS];    // h row -> compact slot (or -1)

// ---------------------------------------------------------------------------
// Helpers
// ---------------------------------------------------------------------------
__device__ __forceinline__ uint32_t smem_to_u32(const void* smem_ptr) {
    uint32_t addr;
    asm("{ .reg .u64 tmp; cvta.to.shared.u64 tmp, %1; cvt.u32.u64 %0, tmp; }"
        : "=r"(addr) : "l"(smem_ptr));
    return addr;
}

__device__ __forceinline__ void cp_async16(uint32_t dst, const void* src, int src_bytes) {
    asm volatile("cp.async.cg.shared.global [%0], [%1], 16, %2;"
                 :: "r"(dst), "l"(src), "r"(src_bytes));
}
#define CP_ASYNC_COMMIT() asm volatile("cp.async.commit_group;" ::: "memory")
#define CP_ASYNC_WAIT_2() asm volatile("cp.async.wait_group 2;" ::: "memory")

#define LDMATRIX_X4(r0, r1, r2, r3, addr) \
    asm volatile("ldmatrix.sync.aligned.m8n8.x4.shared.b16 {%0,%1,%2,%3}, [%4];" \
                 : "=r"(r0), "=r"(r1), "=r"(r2), "=r"(r3) : "r"(addr))

#define MMA_16816(d, a0, a1, a2, a3, b0, b1) \
    asm volatile("mma.sync.aligned.m16n8k16.row.col.f32.f16.f16.f32 " \
                 "{%0,%1,%2,%3}, {%4,%5,%6,%7}, {%8,%9}, {%0,%1,%2,%3};" \
                 : "+f"((d)[0]), "+f"((d)[1]), "+f"((d)[2]), "+f"((d)[3]) \
                 : "r"(a0), "r"(a1), "r"(a2), "r"(a3), "r"(b0), "r"(b1))

__device__ __forceinline__ int is_last(const int* iobs, int r) {
    return (r == NOBS - 1) || (iobs[r + 1] != iobs[r]);
}

// ---------------------------------------------------------------------------
// 1. initA: scanA (blocks < NSB) + loss/rowslot init + weight convert
// ---------------------------------------------------------------------------
__global__ void __launch_bounds__(512) initA_kernel(
    const int* __restrict__ iobs,
    const float* __restrict__ wih, const float* __restrict__ whh) {
    __shared__ int sh[SCAN_BLK];

    if (blockIdx.x < NSB) {
        const int r = blockIdx.x * SCAN_BLK + threadIdx.x;
        sh[threadIdx.x] = (r < NOBS) ? is_last(iobs, r) : 0;
        __syncthreads();
        for (int s = SCAN_BLK / 2; s > 0; s >>= 1) {
            if (threadIdx.x < s) sh[threadIdx.x] += sh[threadIdx.x + s];
            __syncthreads();
        }
        if (threadIdx.x == 0) g_blkcnt[blockIdx.x] = sh[0];
        return;
    }

    const int b = blockIdx.x - NSB;
    const int tid = b * 512 + threadIdx.x;
    const int nthr = 256 * 512;
    if (tid == 0) g_loss = 0.0f;
    for (int i = tid; i < N_ROWS; i += nthr) g_rowslot[i] = -1;

    const int q1 = H3 * K1 / 4;
    const int q2 = H3 * K2 / 4;
    for (int i = tid; i < q1 + q2; i += nthr) {
        float4 v;
        __half2* dst;
        if (i < q1) {
            v = reinterpret_cast<const float4*>(wih)[i];
            dst = reinterpret_cast<__half2*>(&g_Wih_h[(size_t)i * 4]);
        } else {
            v = reinterpret_cast<const float4*>(whh)[i - q1];
            dst = reinterpret_cast<__half2*>(&g_Whh_h[(size_t)(i - q1) * 4]);
        }
        dst[0] = __floats2half2_rn(v.x, v.y);
        dst[1] = __floats2half2_rn(v.z, v.w);
    }
}

// ---------------------------------------------------------------------------
// 2-3. Scan finish
// ---------------------------------------------------------------------------
__global__ void scanB_kernel() {
    if (threadIdx.x == 0) {
        int acc = 0;
        for (int b = 0; b < NSB; b++) { g_blkoff[b] = acc; acc += g_blkcnt[b]; }
        g_Mc = acc;
    }
}

__global__ void __launch_bounds__(SCAN_BLK) scanC_kernel(const int* __restrict__ iobs) {
    __shared__ int sh[SCAN_BLK];
    const int r = blockIdx.x * SCAN_BLK + threadIdx.x;
    const int last = (r < NOBS) ? is_last(iobs, r) : 0;
    sh[threadIdx.x] = last;
    __syncthreads();
    for (int off = 1; off < SCAN_BLK; off <<= 1) {
        int v = (threadIdx.x >= off) ? sh[threadIdx.x - off] : 0;
        __syncthreads();
        sh[threadIdx.x] += v;
        __syncthreads();
    }
    if (r < NOBS) {
        const int slot = g_blkoff[blockIdx.x] + sh[threadIdx.x] - last;  // exclusive
        g_slot[r] = slot;
        if (last) {
            const int i = iobs[r];
            g_cidx[slot] = i;
            g_rowslot[i] = slot;
        }
    }
}

// ---------------------------------------------------------------------------
// 4. Prep: loss (all rows) + feats einsum (last rows, compacted) -> g_gruin
//    Transposed, conflict-free smem staging.
// ---------------------------------------------------------------------------
__global__ void __launch_bounds__(256) prep_kernel(
    const float* __restrict__ p, const float* __restrict__ X,
    const float* __restrict__ M, const int* __restrict__ iobs,
    const float* __restrict__ wprep, const float* __restrict__ bprep) {
    __shared__ float swt[64 * D_IN];   // [k = f*16+j][d]
    __shared__ float sbt[PH * D_IN];   // [j][d]
    __shared__ float sred[256];

    for (int i = threadIdx.x; i < D_IN * 64; i += 256) {
        const int d = i >> 6, k = i & 63;
        swt[k * 64 + d] = wprep[i];
    }
    for (int i = threadIdx.x; i < D_IN * PH; i += 256) {
        const int d = i >> 4, j = i & 15;
        sbt[j * 64 + d] = bprep[i];
    }
    __syncthreads();

    const int d   = threadIdx.x & 63;
    const int sub = threadIdx.x >> 6;   // 0..3
    const int base = blockIdx.x * 32;
    float lacc = 0.0f;

    for (int rr = sub; rr < 32; rr += 4) {
        const int r = base + rr;
        if (r >= NOBS) continue;
        const int i = iobs[r];
        const float mean = p[(size_t)i * 128 + d];
        const float var  = fabsf(p[(size_t)i * 128 + 64 + d]) + 1e-6f;
        const float x    = X[(size_t)r * 64 + d];
        const float m    = M[(size_t)r * 64 + d];
        const float rsv  = rsqrtf(var);
        const float err  = (x - mean) * rsv;
        lacc += 0.5f * (err * err + logf(var)) * m;

        if (!is_last(iobs, r)) continue;

        __half2 hv[8];
        #pragma unroll
        for (int j = 0; j < 16; j += 2) {
            float v0 = sbt[j * 64 + d];
            v0 = fmaf(x,    swt[(j)      * 64 + d], v0);
            v0 = fmaf(mean, swt[(16 + j) * 64 + d], v0);
            v0 = fmaf(var,  swt[(32 + j) * 64 + d], v0);
            v0 = fmaf(err,  swt[(48 + j) * 64 + d], v0);
            float v1 = sbt[(j + 1) * 64 + d];
            v1 = fmaf(x,    swt[(j + 1)      * 64 + d], v1);
            v1 = fmaf(mean, swt[(16 + j + 1) * 64 + d], v1);
            v1 = fmaf(var,  swt[(32 + j + 1) * 64 + d], v1);
            v1 = fmaf(err,  swt[(48 + j + 1) * 64 + d], v1);
            v0 = fmaxf(v0, 0.0f) * m;
            v1 = fmaxf(v1, 0.0f) * m;
            hv[j >> 1] = __floats2half2_rn(v0, v1);
        }
        const int slot = g_slot[r];
        uint4* dst = reinterpret_cast<uint4*>(&g_gruin[(size_t)slot * K1 + d * 16]);
        dst[0] = *reinterpret_cast<uint4*>(&hv[0]);
        dst[1] = *reinterpret_cast<uint4*>(&hv[4]);
    }

    sred[threadIdx.x] = lacc;
    __syncthreads();
    for (int s = 128; s > 0; s >>= 1) {
        if (threadIdx.x < s) sred[threadIdx.x] += sred[threadIdx.x + s];
        __syncthreads();
    }
    if (threadIdx.x == 0) atomicAdd(&g_loss, sred[0]);
}

// ---------------------------------------------------------------------------
// 5. Gather h[cidx[s]] -> fp16 (lean, no smem, MLP=2: 64 thr/row, 2 float4 ea)
// ---------------------------------------------------------------------------
__global__ void __launch_bounds__(256) gather_h_kernel(const float* __restrict__ h) {
    const int idx = blockIdx.x * 256 + threadIdx.x;
    const int s = idx >> 6;              // 64 threads per slot
    if (s >= g_Mc) return;
    const int t = idx & 63;
    const int i = g_cidx[s];
    const float4* src = reinterpret_cast<const float4*>(&h[(size_t)i * HID]);
    const float4 v0 = src[t * 2];
    const float4 v1 = src[t * 2 + 1];
    __half2 hv[4];
    hv[0] = __floats2half2_rn(v0.x, v0.y);
    hv[1] = __floats2half2_rn(v0.z, v0.w);
    hv[2] = __floats2half2_rn(v1.x, v1.y);
    hv[3] = __floats2half2_rn(v1.z, v1.w);
    *reinterpret_cast<uint4*>(&g_hgat[(size_t)s * K2 + t * 8]) =
        *reinterpret_cast<uint4*>(hv);
}

// ---------------------------------------------------------------------------
// 6. FUSED HMMA GEMM over concatenated K (48 chunks = 32 gruin/Wih + 16
//    hgat/Whh), single launch, dynamic M = g_Mc.
//    rz tiles (n0 < 1024): accumulate all 48 chunks -> gi = ir+hr (1 write,
//                          no rmw, fully fp32-accumulated)
//    n  tiles (n0 >= 1024): chunks 0-31 -> gi (in), zero acc,
//                           chunks 32-47 -> gh (hn)
// ---------------------------------------------------------------------------
#define STAGES       4
#define STAGE_BYTES  20480          // A 10240 + B 10240
#define SM_B_OFF     10240

__device__ __forceinline__ void load_stage(uint32_t sm, int stage,
                                           int m0, int n0, int kc,
                                           int tid, int Mrows) {
    const uint32_t base = sm + stage * STAGE_BYTES;
    const bool p1 = kc < 32;
    const int kb = p1 ? kc * 32 : (kc - 32) * 32;   // element offset in K dim
    #pragma unroll
    for (int it = 0; it < 4; it++) {
        const int c = tid + it * 256;           // 0..1023
        const int cc = c & 511;
        const int row = cc >> 2, ch = cc & 3;   // 128 rows x 4 x 16B
        if (c < 512) {  // A
            const int rg = m0 + row;
            const int rc = rg < Mrows ? rg : (Mrows - 1);
            const void* src = p1
                ? (const void*)(g_gruin + (size_t)rc * K1 + kb + ch * 8)
                : (const void*)(g_hgat  + (size_t)rc * K2 + kb + ch * 8);
            cp_async16(base + row * 80 + ch * 16, src, rg < Mrows ? 16 : 0);
        } else {        // B (always in range)
            const void* src = p1
                ? (const void*)(g_Wih_h + (size_t)(n0 + row) * K1 + kb + ch * 8)
                : (const void*)(g_Whh_h + (size_t)(n0 + row) * K2 + kb + ch * 8);
            cp_async16(base + SM_B_OFF + row * 80 + ch * 16, src, 16);
        }
    }
}

__global__ void __launch_bounds__(256, 2) gemm_fused_kernel() {
    const int Mrows = g_Mc;
    const int m0 = blockIdx.y * 128;
    if (m0 >= Mrows) return;                      // surplus m-tiles exit

    extern __shared__ __align__(128) char smem[];   // STAGES * STAGE_BYTES
    const uint32_t sm = smem_to_u32(smem);

    const int tid  = threadIdx.x;
    const int lane = tid & 31;
    const int wid  = tid >> 5;
    const int warp_m = wid & 3;
    const int warp_n = wid >> 2;

    const int n0 = blockIdx.x * 128;
    const bool isN = (n0 >= 1024);

    const uint32_t lrow = lane & 15;
    const uint32_t lcol = (lane >> 4) << 4;
    const uint32_t a_off = (warp_m * 32 + lrow) * 80 + lcol;
    const uint32_t b_off = SM_B_OFF + (warp_n * 64 + lrow) * 80 + lcol;

    float acc[2][8][4];
    #pragma unroll
    for (int mt = 0; mt < 2; mt++)
        #pragma unroll
        for (int nt = 0; nt < 8; nt++)
            #pragma unroll
            for (int e = 0; e < 4; e++) acc[mt][nt][e] = 0.0f;

    #pragma unroll
    for (int s = 0; s < 3; s++) {
        load_stage(sm, s, m0, n0, s, tid, Mrows);
        CP_ASYNC_COMMIT();
    }

    for (int kc = 0; kc < NK_TOT; kc++) {
        const int buf = kc & 3;
        CP_ASYNC_WAIT_2();
        __syncthreads();

        if (kc + 3 < NK_TOT)
            load_stage(sm, (kc + 3) & 3, m0, n0, kc + 3, tid, Mrows);
        CP_ASYNC_COMMIT();

        const uint32_t sA = sm + buf * STAGE_BYTES;

        #pragma unroll
        for (int ks = 0; ks < 2; ks++) {
            const uint32_t k0b = ks * 32;
            uint32_t a[2][4];
            LDMATRIX_X4(a[0][0], a[0][1], a[0][2], a[0][3], sA + a_off + k0b);
            LDMATRIX_X4(a[1][0], a[1][1], a[1][2], a[1][3], sA + a_off + 1280 + k0b);
            uint32_t b[8][2];
            #pragma unroll
            for (int nb = 0; nb < 4; nb++) {
                uint32_t r0, r1, r2, r3;
                LDMATRIX_X4(r0, r1, r2, r3, sA + b_off + nb * 1280 + k0b);
                b[2 * nb][0] = r0; b[2 * nb][1] = r2;
                b[2 * nb + 1][0] = r1; b[2 * nb + 1][1] = r3;
            }
            #pragma unroll
            for (int mt = 0; mt < 2; mt++)
                #pragma unroll
                for (int nt = 0; nt < 8; nt++)
                    MMA_16816(acc[mt][nt],
                              a[mt][0], a[mt][1], a[mt][2], a[mt][3],
                              b[nt][0], b[nt][1]);
        }

        // n-tile seam: after chunk 31 (end of gruin@Wih phase), flush "in"
        // into gi and reset accumulators for the hn phase.
        if (isN && kc == 31) {
            #pragma unroll
            for (int mt = 0; mt < 2; mt++) {
                const int r0 = m0 + warp_m * 32 + mt * 16 + (lane >> 2);
                #pragma unroll
                for (int nt = 0; nt < 8; nt++) {
                    const int col = n0 + warp_n * 64 + nt * 8 + (lane & 3) * 2;
                    if (r0 < Mrows)
                        *reinterpret_cast<__half2*>(&g_gi[(size_t)r0 * H3 + col]) =
                            __floats2half2_rn(acc[mt][nt][0], acc[mt][nt][1]);
                    if (r0 + 8 < Mrows)
                        *reinterpret_cast<__half2*>(&g_gi[(size_t)(r0 + 8) * H3 + col]) =
                            __floats2half2_rn(acc[mt][nt][2], acc[mt][nt][3]);
                    #pragma unroll
                    for (int e = 0; e < 4; e++) acc[mt][nt][e] = 0.0f;
                }
            }
        }
    }

    // final epilogue: rz tiles -> gi (ir+hr / iz+hz), n tiles -> gh (hn)
    __half* Cb = isN ? g_gh : g_gi;
    #pragma unroll
    for (int mt = 0; mt < 2; mt++) {
        const int r0 = m0 + warp_m * 32 + mt * 16 + (lane >> 2);
        #pragma unroll
        for (int nt = 0; nt < 8; nt++) {
            const int col = n0 + warp_n * 64 + nt * 8 + (lane & 3) * 2;
            if (r0 < Mrows)
                *reinterpret_cast<__half2*>(&Cb[(size_t)r0 * H3 + col]) =
                    __floats2half2_rn(acc[mt][nt][0], acc[mt][nt][1]);
            if (r0 + 8 < Mrows)
                *reinterpret_cast<__half2*>(&Cb[(size_t)(r0 + 8) * H3 + col]) =
                    __floats2half2_rn(acc[mt][nt][2], acc[mt][nt][3]);
        }
    }
}

// ---------------------------------------------------------------------------
// 7. Unified output (champion v1): 4 rows/block, 64 thr/row, 2 float4/thread
//    gi: [0,512)=ir+hr, [512,1024)=iz+hz, [1024,1536)=in; gh: [1024,1536)=hn
// ---------------------------------------------------------------------------
__global__ void __launch_bounds__(256) out_kernel(
    const float* __restrict__ h,
    const float* __restrict__ bih, const float* __restrict__ bhh,
    float* __restrict__ out, int has_loss) {
    if (has_loss && blockIdx.x == 0 && threadIdx.x == 0)
        out[(size_t)N_ROWS * HID] = g_loss;

    const int row = blockIdx.x * 4 + (threadIdx.x >> 6);
    if (row >= N_ROWS) return;
    const int t = threadIdx.x & 63;
    const int s = g_rowslot[row];

    const float4* hrow4 = reinterpret_cast<const float4*>(&h[(size_t)row * HID]);
    float4* orow4 = reinterpret_cast<float4*>(&out[(size_t)row * HID]);

    if (s < 0) {                                 // not updated: plain copy
        const float4 c0 = hrow4[t];
        const float4 c1 = hrow4[t + 64];
        orow4[t] = c0;
        orow4[t + 64] = c1;
        return;
    }

    const __half2* gi = reinterpret_cast<const __half2*>(&g_gi[(size_t)s * H3]);
    const __half2* gh = reinterpret_cast<const __half2*>(&g_gh[(size_t)s * H3]);
    const float4* b_ih4 = reinterpret_cast<const float4*>(bih);
    const float4* b_hh4 = reinterpret_cast<const float4*>(bhh);

    #pragma unroll
    for (int k = 0; k < 2; k++) {
        const int q = t + k * 64;               // float4 index within row
        const int j0 = 2 * q, j1 = 2 * q + 1;
        const float2 sr0 = __half22float2(gi[j0]),       sr1 = __half22float2(gi[j1]);
        const float2 sz0 = __half22float2(gi[256 + j0]), sz1 = __half22float2(gi[256 + j1]);
        const float2 in0 = __half22float2(gi[512 + j0]), in1 = __half22float2(gi[512 + j1]);
        const float2 hn0 = __half22float2(gh[512 + j0]), hn1 = __half22float2(gh[512 + j1]);
        const float4 bir = b_ih4[q],       bhr = b_hh4[q];
        const float4 biz = b_ih4[128 + q], bhz = b_hh4[128 + q];
        const float4 bin = b_ih4[256 + q], bhn = b_hh4[256 + q];
        const float4 hp = hrow4[q];

        const float irs[4] = {sr0.x + bir.x + bhr.x, sr0.y + bir.y + bhr.y,
                              sr1.x + bir.z + bhr.z, sr1.y + bir.w + bhr.w};
        const float izs[4] = {sz0.x + biz.x + bhz.x, sz0.y + biz.y + bhz.y,
                              sz1.x + biz.z + bhz.z, sz1.y + biz.w + bhz.w};
        const float ins[4] = {in0.x + bin.x, in0.y + bin.y, in1.x + bin.z, in1.y + bin.w};
        const float hns[4] = {hn0.x + bhn.x, hn0.y + bhn.y, hn1.x + bhn.z, hn1.y + bhn.w};

        float rr[4], zz[4], nn[4];
        #pragma unroll
        for (int e = 0; e < 4; e++) {
            rr[e] = 1.0f / (1.0f + expf(-irs[e]));
            zz[e] = 1.0f / (1.0f + expf(-izs[e]));
            nn[e] = tanhf(ins[e] + rr[e] * hns[e]);
        }
        float4 o;
        o.x = (1.0f - zz[0]) * nn[0] + zz[0] * hp.x;
        o.y = (1.0f - zz[1]) * nn[1] + zz[1] * hp.y;
        o.z = (1.0f - zz[2]) * nn[2] + zz[2] * hp.z;
        o.w = (1.0f - zz[3]) * nn[3] + zz[3] * hp.w;
        orow4[q] = o;
    }
}

// ---------------------------------------------------------------------------
// Launch — single stream, 7 nodes
// ---------------------------------------------------------------------------
extern "C" void kernel_launch(void* const* d_in, const int* in_sizes, int n_in,
                              void* d_out, int out_size) {
    const float* h     = (const float*)d_in[0];
    const float* p     = (const float*)d_in[1];
    const float* X     = (const float*)d_in[2];
    const float* M     = (const float*)d_in[3];
    const int*   iobs  = (const int*)  d_in[4];
    const float* wprep = (const float*)d_in[5];
    const float* bprep = (const float*)d_in[6];
    const float* wih   = (const float*)d_in[7];
    const float* whh   = (const float*)d_in[8];
    const float* bih   = (const float*)d_in[9];
    const float* bhh   = (const float*)d_in[10];
    float* out = (float*)d_out;

    static bool init_done = false;
    if (!init_done) {
        cudaFuncSetAttribute(gemm_fused_kernel,
                             cudaFuncAttributeMaxDynamicSharedMemorySize,
                             STAGES * STAGE_BYTES);
        init_done = true;
    }

    // 1. scanA + init (loss, rowslot) + weight convert
    initA_kernel<<<NSB + 256, 512>>>(iobs, wih, whh);

    // 2-3. scan finish
    scanB_kernel<<<1, 32>>>();
    scanC_kernel<<<NSB, SCAN_BLK>>>(iobs);

    // 4. prep: loss + gru_in (compacted, conflict-free smem)
    prep_kernel<<<(NOBS + 31) / 32, 256>>>(p, X, M, iobs, wprep, bprep);

    // 5. gather h[cidx] -> fp16 (lean, vectorized)
    gather_h_kernel<<<(NOBS * 64 + 255) / 256, 256>>>(h);

    // 6. fused GEMM: concatenated-K for r,z (single write), two-phase for n
    gemm_fused_kernel<<<dim3(12, MTILES), 256, STAGES * STAGE_BYTES>>>();

    // 7. unified output (+loss)
    out_kernel<<<(N_ROWS + 3) / 4, 256>>>(h, bih, bhh, out,
                                          out_size > N_ROWS * HID ? 1 : 0);
}